// round 15
// baseline (speedup 1.0000x reference)
#include <cuda_runtime.h>

#define NB       262144
#define THREADS  256
#define ROWS_PER_TILE 128
#define NTILES   (NB / ROWS_PER_TILE)   // 2048
#define GRID_X   148

typedef unsigned long long u64;

// ---- packed f32x2 helpers (SASS FFMA2) ----
__device__ __forceinline__ u64 ffma2(u64 a, u64 b, u64 c) {
    u64 d;
    asm("fma.rn.f32x2 %0, %1, %2, %3;" : "=l"(d) : "l"(a), "l"(b), "l"(c));
    return d;
}
__device__ __forceinline__ u64 pack2(float lo, float hi) {
    u64 d;
    asm("mov.b64 %0, {%1, %2};" : "=l"(d) : "f"(lo), "f"(hi));
    return d;
}
__device__ __forceinline__ void unpack2(u64 a, float& lo, float& hi) {
    asm("mov.b64 {%0, %1}, %2;" : "=f"(lo), "=f"(hi) : "l"(a));
}

// ---- smem layout (u64 units) ----
// WD [0,12288)      : u64 Wdup[l][k][j] = {W_l[j][k+1], W_l[j][k+1]}  (duplicated pairs)
// H0 [12288,16384)  : u64 h-scratch A [64 k][64 row-pairs]  ({h_rowA, h_rowB} per unit)
// H1 [16384,20480)  : u64 h-scratch B (reused as float partial[8][128] in div combine)
// V0 [20480,24576)  : u64 v-scratch A
// V1 [24576,28672)  : u64 v-scratch B
#define U_WD  0
#define U_H0  12288
#define U_H1  16384
#define U_V0  20480
#define U_V1  24576
#define SMEM_BYTES (28672 * 8)   // 229,376 B (cap 232,448)

__global__ void __launch_bounds__(THREADS, 1)
odefunc_kernel(const float* __restrict__ t_p,
               const float* __restrict__ z,
               const float* __restrict__ e,
               const float* __restrict__ W0g, const float* __restrict__ b0g,
               const float* __restrict__ W1g, const float* __restrict__ b1g,
               const float* __restrict__ W2g, const float* __restrict__ b2g,
               float* __restrict__ out)
{
    extern __shared__ __align__(16) u64 sm[];

    const int tid = threadIdx.x;
    const int jo  = tid >> 5;        // warp id: owns outputs j = jo*8 .. jo*8+7
    const int r   = tid & 31;        // owns row-pairs 2r, 2r+1 -> rows 4r .. 4r+3
    const float t = t_p[0];

    // ---- one-time weight staging: duplicated pairs ----
    {
        float* Wd = reinterpret_cast<float*>(sm + U_WD);
        const float* Wg[3] = { W0g, W1g, W2g };
#pragma unroll 1
        for (int l = 0; l < 3; ++l) {
            for (int idx = tid; idx < 4096; idx += THREADS) {
                int j = idx >> 6, k = idx & 63;
                float w = Wg[l][j * 65 + k + 1];
                Wd[(((l * 64 + k) * 64) + j) * 2 + 0] = w;
                Wd[(((l * 64 + k) * 64) + j) * 2 + 1] = w;
            }
        }
    }
    __syncthreads();

    const u64 tt = pack2(t, t);
    u64 ah[2][8], av[2][8];          // [row-pair rri][output jj]

    for (int tile = blockIdx.x; tile < NTILES; tile += GRID_X) {
        const size_t rowbase = (size_t)tile * ROWS_PER_TILE;
        const size_t row0 = rowbase + 4 * r;     // this thread's 4 rows: row0..row0+3

        // ---- stage z -> H0, e -> V0 as row-pair units {x_rowA, x_rowB} ----
        // (previous tile's readers of H0/V0 are past the post-loop barrier)
        {
            const float4* z0 = reinterpret_cast<const float4*>(z + (row0 + 0) * 64 + jo * 8);
            const float4* z1 = reinterpret_cast<const float4*>(z + (row0 + 1) * 64 + jo * 8);
            const float4* z2 = reinterpret_cast<const float4*>(z + (row0 + 2) * 64 + jo * 8);
            const float4* z3 = reinterpret_cast<const float4*>(z + (row0 + 3) * 64 + jo * 8);
            const float4* e0 = reinterpret_cast<const float4*>(e + (row0 + 0) * 64 + jo * 8);
            const float4* e1 = reinterpret_cast<const float4*>(e + (row0 + 1) * 64 + jo * 8);
            const float4* e2 = reinterpret_cast<const float4*>(e + (row0 + 2) * 64 + jo * 8);
            const float4* e3 = reinterpret_cast<const float4*>(e + (row0 + 3) * 64 + jo * 8);
#pragma unroll
            for (int q = 0; q < 2; ++q) {
                float4 a = z0[q], b = z1[q], c = z2[q], d = z3[q];
                ulonglong2* H = reinterpret_cast<ulonglong2*>(sm + U_H0 + (jo * 8 + 4 * q) * 64 + 2 * r);
                H[0]  = make_ulonglong2(pack2(a.x, b.x), pack2(c.x, d.x));
                H[32] = make_ulonglong2(pack2(a.y, b.y), pack2(c.y, d.y));
                H[64] = make_ulonglong2(pack2(a.z, b.z), pack2(c.z, d.z));
                H[96] = make_ulonglong2(pack2(a.w, b.w), pack2(c.w, d.w));
                float4 p = e0[q], s = e1[q], u = e2[q], v = e3[q];
                ulonglong2* V = reinterpret_cast<ulonglong2*>(sm + U_V0 + (jo * 8 + 4 * q) * 64 + 2 * r);
                V[0]  = make_ulonglong2(pack2(p.x, s.x), pack2(u.x, v.x));
                V[32] = make_ulonglong2(pack2(p.y, s.y), pack2(u.y, v.y));
                V[64] = make_ulonglong2(pack2(p.z, s.z), pack2(u.z, v.z));
                V[96] = make_ulonglong2(pack2(p.w, s.w), pack2(u.w, v.w));
            }
        }

        // ---- three fused primal+tangent passes ----
#pragma unroll 1
        for (int pass = 0; pass < 3; ++pass) {
            __syncthreads();

            const u64* hin  = sm + ((pass & 1) ? U_H1 : U_H0);
            u64*       hout = sm + ((pass & 1) ? U_H0 : U_H1);
            const u64* vin  = sm + ((pass & 1) ? U_V1 : U_V0);
            u64*       vout = sm + ((pass & 1) ? U_V0 : U_V1);
            const u64* W    = sm + U_WD + pass * 4096;
            const float* Wt = (pass == 0) ? W0g : (pass == 1) ? W1g : W2g;

            // init: h gets k=0 term fma(t, W[j][0], 0) in both row lanes; v starts 0
#pragma unroll
            for (int jj = 0; jj < 8; ++jj) {
                float w0 = Wt[(jo * 8 + jj) * 65];
                u64 ini = ffma2(tt, pack2(w0, w0), 0ull);
                ah[0][jj] = ini;  ah[1][jj] = ini;
                av[0][jj] = 0ull; av[1][jj] = 0ull;
            }

            // mainloop: k strictly ascending; acts are natural row-pairs (no packs)
#pragma unroll 4
            for (int k = 0; k < 64; ++k) {
                ulonglong2 hh = *reinterpret_cast<const ulonglong2*>(hin + k * 64 + 2 * r);
                ulonglong2 vv = *reinterpret_cast<const ulonglong2*>(vin + k * 64 + 2 * r);
                const ulonglong2* wd = reinterpret_cast<const ulonglong2*>(W + k * 64 + jo * 8);
#pragma unroll
                for (int q = 0; q < 4; ++q) {
                    ulonglong2 w = wd[q];                 // {w_{2q}dup, w_{2q+1}dup}
                    ah[0][2*q]   = ffma2(hh.x, w.x, ah[0][2*q]);
                    ah[0][2*q+1] = ffma2(hh.x, w.y, ah[0][2*q+1]);
                    ah[1][2*q]   = ffma2(hh.y, w.x, ah[1][2*q]);
                    ah[1][2*q+1] = ffma2(hh.y, w.y, ah[1][2*q+1]);
                    av[0][2*q]   = ffma2(vv.x, w.x, av[0][2*q]);
                    av[0][2*q+1] = ffma2(vv.x, w.y, av[0][2*q+1]);
                    av[1][2*q]   = ffma2(vv.y, w.x, av[1][2*q]);
                    av[1][2*q+1] = ffma2(vv.y, w.y, av[1][2*q+1]);
                }
            }

            // ---- epilogues ----
            if (pass < 2) {
                const float* bsel = (pass == 0) ? b0g : b1g;
#pragma unroll
                for (int jj = 0; jj < 8; ++jj) {
                    float b = bsel[jo * 8 + jj];          // uniform LDG, L1-hot
                    u64 ho[2], vo[2];
#pragma unroll
                    for (int rri = 0; rri < 2; ++rri) {
                        float h0, h1; unpack2(ah[rri][jj], h0, h1);
                        float v0, v1; unpack2(av[rri][jj], v0, v1);
                        h0 += b; h1 += b;                 // bias once (bit-exact)
                        v0 = (h0 > 0.0f) ? v0 : 0.0f;     // relu-mask on tangent
                        v1 = (h1 > 0.0f) ? v1 : 0.0f;
                        ho[rri] = pack2(fmaxf(h0, 0.0f), fmaxf(h1, 0.0f));
                        vo[rri] = pack2(v0, v1);
                    }
                    *reinterpret_cast<ulonglong2*>(hout + (jo * 8 + jj) * 64 + 2 * r) =
                        make_ulonglong2(ho[0], ho[1]);
                    *reinterpret_cast<ulonglong2*>(vout + (jo * 8 + jj) * 64 + 2 * r) =
                        make_ulonglong2(vo[0], vo[1]);
                }
            } else {
                // z_dot = h + b2 -> gmem; div partial = dot(v, e-slice) per row
                const float4* b4 = reinterpret_cast<const float4*>(b2g + jo * 8);
                float4 ba = b4[0], bb = b4[1];
                float* partial = reinterpret_cast<float*>(sm + U_H1);  // [8 jo][128 rows]
#pragma unroll
                for (int rri = 0; rri < 2; ++rri) {
                    const size_t rA = row0 + 2 * rri;     // lane-lo row
                    const size_t rB = rA + 1;             // lane-hi row
                    float a0, c0, a1, c1, a2, c2, a3, c3, a4, c4, a5, c5, a6, c6, a7, c7;
                    unpack2(ah[rri][0], a0, c0); unpack2(ah[rri][1], a1, c1);
                    unpack2(ah[rri][2], a2, c2); unpack2(ah[rri][3], a3, c3);
                    unpack2(ah[rri][4], a4, c4); unpack2(ah[rri][5], a5, c5);
                    unpack2(ah[rri][6], a6, c6); unpack2(ah[rri][7], a7, c7);
                    float4* oA = reinterpret_cast<float4*>(out + rA * 64 + jo * 8);
                    float4* oB = reinterpret_cast<float4*>(out + rB * 64 + jo * 8);
                    oA[0] = make_float4(a0 + ba.x, a1 + ba.y, a2 + ba.z, a3 + ba.w);
                    oA[1] = make_float4(a4 + bb.x, a5 + bb.y, a6 + bb.z, a7 + bb.w);
                    oB[0] = make_float4(c0 + ba.x, c1 + ba.y, c2 + ba.z, c3 + ba.w);
                    oB[1] = make_float4(c4 + bb.x, c5 + bb.y, c6 + bb.z, c7 + bb.w);

                    const float4* eA = reinterpret_cast<const float4*>(e + rA * 64 + jo * 8);
                    const float4* eB = reinterpret_cast<const float4*>(e + rB * 64 + jo * 8);
                    float4 ea0 = eA[0], ea1 = eA[1], eb0 = eB[0], eb1 = eB[1];
                    u64 d = 0ull;
                    d = ffma2(pack2(ea0.x, eb0.x), av[rri][0], d);
                    d = ffma2(pack2(ea0.y, eb0.y), av[rri][1], d);
                    d = ffma2(pack2(ea0.z, eb0.z), av[rri][2], d);
                    d = ffma2(pack2(ea0.w, eb0.w), av[rri][3], d);
                    d = ffma2(pack2(ea1.x, eb1.x), av[rri][4], d);
                    d = ffma2(pack2(ea1.y, eb1.y), av[rri][5], d);
                    d = ffma2(pack2(ea1.z, eb1.z), av[rri][6], d);
                    d = ffma2(pack2(ea1.w, eb1.w), av[rri][7], d);
                    float dA, dB; unpack2(d, dA, dB);
                    partial[jo * 128 + 4 * r + 2 * rri]     = dA;
                    partial[jo * 128 + 4 * r + 2 * rri + 1] = dB;
                }
            }
        }

        __syncthreads();
        if (jo == 0) {
            const float* partial = reinterpret_cast<const float*>(sm + U_H1);
#pragma unroll
            for (int rr2 = 0; rr2 < 4; ++rr2) {
                const int rloc = r + 32 * rr2;
                float s = 0.0f;
#pragma unroll
                for (int g = 0; g < 8; ++g)
                    s += partial[g * 128 + rloc];
                out[(size_t)NB * 64 + rowbase + rloc] = -s;
            }
        }
    }
}

extern "C" void kernel_launch(void* const* d_in, const int* in_sizes, int n_in,
                              void* d_out, int out_size) {
    const float* t  = (const float*)d_in[0];
    const float* z  = (const float*)d_in[1];
    const float* e  = (const float*)d_in[2];
    const float* W0 = (const float*)d_in[3];
    const float* b0 = (const float*)d_in[4];
    const float* W1 = (const float*)d_in[5];
    const float* b1 = (const float*)d_in[6];
    const float* W2 = (const float*)d_in[7];
    const float* b2 = (const float*)d_in[8];
    float* out = (float*)d_out;

    cudaFuncSetAttribute(odefunc_kernel,
                         cudaFuncAttributeMaxDynamicSharedMemorySize, SMEM_BYTES);

    odefunc_kernel<<<GRID_X, THREADS, SMEM_BYTES>>>(t, z, e, W0, b0, W1, b1, W2, b2, out);
}